// round 7
// baseline (speedup 1.0000x reference)
#include <cuda_runtime.h>

// HATS two-phase global-CSR:
//   kernel A: 1 thread/event -> global bins (atomic slot alloc)
//   kernel B: 1 warp/bin -> all causal windowed pairs via shuffles -> 49 outputs
// events [B, T, 4] (x,y,t,p) float32, lengths int32[B]
// out    [B, NC=432, 2, 7, 7] float32
#define RNB     3
#define SNB     7               // 2R+1
#define SS      (SNB * SNB)     // 49
#define GW      24              // 240/10
#define NC      432             // 18*24
#define NBIN    (NC * 2)        // 864 (cell, polarity) bins
#define TAU_F   1e6f
#define DELTA_T 1e5f
#define MAXB    8
#define CAP     16              // per-bin capacity (lambda~1.8; P(overflow) ~ 1e-9)
#define NTA     512             // kernel A threads
#define WPB     16              // kernel B warps per block (even)
#define NTB     (WPB * 32)

// Global scratch (statically zero-initialized; kernel B re-zeroes g_n each run).
__device__ int    g_n[MAXB * NBIN];
__device__ float2 g_ev[MAXB * NBIN * CAP];   // (t, bitcast(idx<<16|x<<8|y))

__global__ __launch_bounds__(NTA)
void hats_binA(const float4* __restrict__ ev, const int* __restrict__ lengths,
               int T) {
    const int b = blockIdx.y;
    const int i = blockIdx.x * NTA + threadIdx.x;
    if (i >= T || i >= lengths[b]) return;
    float4 v = ev[(size_t)b * T + i];
    // bin = (floor(y/10)*24 + floor(x/10))*2 + p  (fp32 exact for these ranges)
    float cx = floorf(v.x * 0.1f);
    float cy = floorf(v.y * 0.1f);
    int bin = (int)fmaf(fmaf(cy, (float)GW, cx), 2.0f, v.w);
    int gb = b * NBIN + bin;
    int pos = atomicAdd(&g_n[gb], 1);
    if (pos < CAP)
        g_ev[gb * CAP + pos] =
            make_float2(v.z, __int_as_float((i << 16) | ((int)v.x << 8) | (int)v.y));
}

__global__ __launch_bounds__(NTB)
void hats_pairB(float* __restrict__ hist, int nbg) {
    __shared__ float s_acc[WPB][SS + 3];   // pad to 52 (bank spread)

    const int b    = blockIdx.x / nbg;
    const int bin0 = (blockIdx.x % nbg) * WPB;
    const int lane = threadIdx.x & 31;
    const int w    = threadIdx.x >> 5;
    const int gb   = b * NBIN + bin0 + w;

    // read both counts needed by this warp BEFORE anyone resets
    const int n_self = g_n[gb];
    const int n_part = g_n[gb ^ 1];
    __syncthreads();
    if (lane == 0) g_n[gb] = 0;            // ready for next graph replay

    const int n = min(n_self, CAP);

    // each lane holds one event of this bin
    float ti = 0.0f;
    int   pi = 0;
    if (lane < n) {
        float2 e2 = g_ev[gb * CAP + lane];
        ti = e2.x;
        pi = __float_as_int(e2.y);
    }
    const int idx_i = pi >> 16;
    const int xi = (pi >> 8) & 0xFF;
    const int yi = pi & 0xFF;
    const bool act = lane < n;

    s_acc[w][lane] = 0.0f;
    if (lane < SS - 32) s_acc[w][lane + 32] = 0.0f;
    __syncwarp();

    const float inv_tau = 1.0f / TAU_F;
    for (int j = 0; j < n; ++j) {
        float tj = __shfl_sync(0xffffffffu, ti, j);
        int   pj = __shfl_sync(0xffffffffu, pi, j);
        if (act && (pj >> 16) <= idx_i && ti - tj <= DELTA_T) {
            int dx = ((pj >> 8) & 0xFF) - xi + RNB;
            int dy = (pj & 0xFF) - yi + RNB;
            if ((unsigned)dx < SNB && (unsigned)dy < SNB)
                atomicAdd(&s_acc[w][dy * SNB + dx], __expf((tj - ti) * inv_tau));
        }
    }
    __syncwarp();

    // normalize by total events in this cell (both polarities), write exclusive 49
    int ccnt = n_self + n_part;
    float inv = 1.0f / (float)(ccnt > 0 ? ccnt : 1);
    float* __restrict__ o = hist + (size_t)gb * SS;
    o[lane] = s_acc[w][lane] * inv;
    if (lane < SS - 32) o[lane + 32] = s_acc[w][lane + 32] * inv;
}

extern "C" void kernel_launch(void* const* d_in, const int* in_sizes, int n_in,
                              void* d_out, int out_size) {
    const float4* events  = (const float4*)d_in[0];   // [B, T, 4]
    const int*    lengths = (const int*)d_in[1];      // [B]

    int B = in_sizes[1];
    int T = in_sizes[0] / (4 * B);

    dim3 gridA((T + NTA - 1) / NTA, B);
    hats_binA<<<gridA, NTA>>>(events, lengths, T);

    int nbg = NBIN / WPB;                              // 54 groups per batch
    hats_pairB<<<B * nbg, NTB>>>((float*)d_out, nbg);
}